// round 2
// baseline (speedup 1.0000x reference)
#include <cuda_runtime.h>

// Radix-64 Fast Walsh-Hadamard Transform, N=4096 fp32.
// 64 threads per row, 64 elements per thread:
//   6 stages in registers (bits 0-5)  -> ONE smem exchange -> 6 stages (bits 6-11).
// Normalized: output scaled by 2^-6.
//
// Smem layout: pitch 68 floats per thread-row.
//   write: addr = tr*68 + i   (STS.128, phases tile all 32 banks)
//   read : addr = i*68 + tr   (LDS.32, banks l + 4i -> conflict-free)

#define HN           4096
#define TPR          64          // threads per row
#define EPT          64          // elements per thread
#define ROWS_PER_CTA 2
#define NTHREADS     (TPR * ROWS_PER_CTA)   // 128
#define PITCH        68          // floats; 68*4 = 272 B per thread-row
#define SROW_FLOATS  (TPR * PITCH)          // 4352

__global__ __launch_bounds__(NTHREADS, 5)
void fwht64_kernel(const float* __restrict__ X, float* __restrict__ Y)
{
    __shared__ float s[ROWS_PER_CTA][SROW_FLOATS];   // 2 * 17408 B = 34816 B

    const int t  = threadIdx.x;
    const int r  = t >> 6;        // row within CTA
    const int tr = t & 63;        // thread within row

    const size_t row = (size_t)blockIdx.x * ROWS_PER_CTA + r;
    const float* __restrict__ x = X + row * HN;
    float*       __restrict__ y = Y + row * HN;

    float v[EPT];

    // ---- Load: thread owns n = tr*64 + i  (bits 0..5 in registers) ----
    {
        const float4* __restrict__ xv =
            reinterpret_cast<const float4*>(x + tr * EPT);
        #pragma unroll
        for (int i = 0; i < 16; i++) {
            float4 a = __ldcs(xv + i);     // streaming: read-once data
            v[4*i+0] = a.x; v[4*i+1] = a.y;
            v[4*i+2] = a.z; v[4*i+3] = a.w;
        }
    }

    // ---- 6 butterfly stages in registers (element-index bits 0..5) ----
    #pragma unroll
    for (int st = 1; st < EPT; st <<= 1) {
        #pragma unroll
        for (int i = 0; i < EPT; i++) {
            if (!(i & st)) {
                float a = v[i], b = v[i ^ st];
                v[i]      = a + b;
                v[i ^ st] = a - b;
            }
        }
    }

    // ---- Exchange: write n = tr*64+i, read n = i*64+tr ----
    float* __restrict__ sr = s[r];
    {
        float4* __restrict__ sw =
            reinterpret_cast<float4*>(sr + tr * PITCH);   // 272B-aligned
        #pragma unroll
        for (int i = 0; i < 16; i++)
            sw[i] = make_float4(v[4*i+0], v[4*i+1], v[4*i+2], v[4*i+3]);
    }
    __syncthreads();

    #pragma unroll
    for (int i = 0; i < EPT; i++)
        v[i] = sr[i * PITCH + tr];

    // ---- 6 butterfly stages in registers (element-index bits 6..11) ----
    #pragma unroll
    for (int st = 1; st < EPT; st <<= 1) {
        #pragma unroll
        for (int i = 0; i < EPT; i++) {
            if (!(i & st)) {
                float a = v[i], b = v[i ^ st];
                v[i]      = a + b;
                v[i ^ st] = a - b;
            }
        }
    }

    // ---- Store: n = i*64 + tr ; lanes cover consecutive addresses -> 128B/warp
    #pragma unroll
    for (int i = 0; i < EPT; i++)
        __stcs(&y[i * TPR + tr], v[i] * 0.015625f);   // * 2^-6 (normalized)
}

extern "C" void kernel_launch(void* const* d_in, const int* in_sizes, int n_in,
                              void* d_out, int out_size)
{
    const float* X = (const float*)d_in[0];   // [8192, 4096] fp32
    // d_in[1] is the dense Hadamard matrix H -- unused (FWHT).
    float* Y = (float*)d_out;

    const int rows = in_sizes[0] / HN;        // 8192
    fwht64_kernel<<<rows / ROWS_PER_CTA, NTHREADS>>>(X, Y);
}

// round 4
// speedup vs baseline: 1.2134x; 1.2134x over previous
#include <cuda_runtime.h>

// Fast Walsh-Hadamard Transform, one row (N=4096 fp32) per CTA, 256 threads.
// 12 butterfly stages:
//   bits 0-3 : registers        (thread owns n = t*16 + i)
//   bits 4-7 : warp shuffles    (= lane bits 0-3, no smem traffic)
//   exchange : one skewed smem transpose (single __syncthreads)
//   bits 8-11: registers        (thread owns n = i*256 + t)
// Output scaled by 2^-6 (normalized Hadamard).

#define HN       4096
#define NTHREADS 256
#define RPT      16
#define SMEM_FLOATS (HN + (HN >> 4))   // skew addr(n) = n + (n>>4): 4352 floats

__global__ __launch_bounds__(NTHREADS, 4)
void fwht_shfl_kernel(const float* __restrict__ X, float* __restrict__ Y)
{
    __shared__ float s[SMEM_FLOATS];

    const int row = blockIdx.x;
    const float* __restrict__ x = X + (size_t)row * HN;
    float*       __restrict__ y = Y + (size_t)row * HN;
    const int t = threadIdx.x;
    const int l = t & 31;

    float v[RPT];

    // ---- Load: n = t*16 + i ----
    {
        const float4* __restrict__ xv = reinterpret_cast<const float4*>(x + t * RPT);
        float4 a0 = xv[0], a1 = xv[1], a2 = xv[2], a3 = xv[3];
        v[0]=a0.x; v[1]=a0.y; v[2]=a0.z; v[3]=a0.w;
        v[4]=a1.x; v[5]=a1.y; v[6]=a1.z; v[7]=a1.w;
        v[8]=a2.x; v[9]=a2.y; v[10]=a2.z; v[11]=a2.w;
        v[12]=a3.x; v[13]=a3.y; v[14]=a3.z; v[15]=a3.w;
    }

    // ---- Stages: element bits 0..3 in registers ----
    #pragma unroll
    for (int st = 1; st < RPT; st <<= 1) {
        #pragma unroll
        for (int i = 0; i < RPT; i++) {
            if (!(i & st)) {
                float a = v[i], b = v[i ^ st];
                v[i]      = a + b;
                v[i ^ st] = a - b;
            }
        }
    }

    // ---- Stages: element bits 4..7 == lane bits 0..3, via shfl.xor ----
    // pair (a,b) -> (a+b, a-b): lane with bit clear holds a.
    #pragma unroll
    for (int m = 1; m <= 8; m <<= 1) {
        const float sgn = (l & m) ? -1.0f : 1.0f;
        #pragma unroll
        for (int i = 0; i < RPT; i++) {
            float other = __shfl_xor_sync(0xffffffffu, v[i], m);
            v[i] = fmaf(sgn, v[i], other);   // bit=0: v+other ; bit=1: other-v
        }
    }

    // ---- Exchange: write n = t*16+i, read n = i*256+t  (skew n + (n>>4)) ----
    {
        const int wb = t * 17;               // banks 17t mod 32: conflict-free
        #pragma unroll
        for (int i = 0; i < RPT; i++) s[wb + i] = v[i];
    }
    __syncthreads();
    {
        const int rb = t + (t >> 4);         // addr = i*272 + t + (t>>4)
        #pragma unroll
        for (int i = 0; i < RPT; i++) v[i] = s[i * 272 + rb];
    }

    // ---- Stages: element bits 8..11 in registers ----
    #pragma unroll
    for (int st = 1; st < RPT; st <<= 1) {
        #pragma unroll
        for (int i = 0; i < RPT; i++) {
            if (!(i & st)) {
                float a = v[i], b = v[i ^ st];
                v[i]      = a + b;
                v[i ^ st] = a - b;
            }
        }
    }

    // ---- Store: n = i*256 + t (coalesced 128B per warp per i), * 2^-6 ----
    #pragma unroll
    for (int i = 0; i < RPT; i++)
        y[i * 256 + t] = v[i] * 0.015625f;
}

extern "C" void kernel_launch(void* const* d_in, const int* in_sizes, int n_in,
                              void* d_out, int out_size)
{
    const float* X = (const float*)d_in[0];   // [8192, 4096] fp32
    // d_in[1]: dense Hadamard matrix H -- unused (FWHT).
    float* Y = (float*)d_out;

    const int rows = in_sizes[0] / HN;        // 8192
    fwht_shfl_kernel<<<rows, NTHREADS>>>(X, Y);
}

// round 5
// speedup vs baseline: 1.5574x; 1.2835x over previous
#include <cuda_runtime.h>

// Fast Walsh-Hadamard Transform, N=4096 fp32, one row per 256-thread CTA.
// All 12 stages in registers across 3 rounds; bit ownership chosen so that
// EVERY global memory instruction is lane-contiguous (no strided LDG):
//   round 1: bits {0,1,7,8}   loads: LDG.128, warp reads 512B contiguous
//   round 2: bits {2,3,4,5}   via swizzled smem exchange
//   round 3: bits {6,9,10,11} via swizzled smem exchange; scalar coalesced STG
// Smem uses XOR swizzle on float4 slots:  s' = s ^ ((s>>4)&7)  -> all four
// access patterns (vec write, scalar read, scalar write, scalar read) are
// bank-conflict-free.  Output scaled by 2^-6 (normalized Hadamard).

#define HN       4096
#define NTHREADS 256
#define RPT      16

__global__ __launch_bounds__(NTHREADS, 6)
void fwht_kernel(const float* __restrict__ X, float* __restrict__ Y)
{
    __shared__ float4 s4[HN / 4];              // 16 KB, no padding needed
    float* const sf = reinterpret_cast<float*>(s4);

    const size_t row = blockIdx.x;
    const float* __restrict__ x = X + row * HN;
    float*       __restrict__ y = Y + row * HN;

    const int t = threadIdx.x;
    const int w = t >> 5;          // warp 0..7
    const int l = t & 31;          // lane

    float v[RPT];

    // ---- Round 1 load: instr j reads float4 slot  w*128 + j*32 + l ----
    // (warp-contiguous 512B per instruction -> 4 L1 wavefronts each)
    {
        const float4* __restrict__ xv = reinterpret_cast<const float4*>(x);
        #pragma unroll
        for (int j = 0; j < 4; j++) {
            float4 a = xv[w * 128 + j * 32 + l];
            v[4*j+0] = a.x; v[4*j+1] = a.y; v[4*j+2] = a.z; v[4*j+3] = a.w;
        }
    }
    // reg index r = j*4 + k  maps to n-bits: r0,r1 = n0,n1 ; r2,r3 = n7,n8
    #pragma unroll
    for (int st = 1; st < RPT; st <<= 1) {
        #pragma unroll
        for (int i = 0; i < RPT; i++) {
            if (!(i & st)) {
                float a = v[i], b = v[i ^ st];
                v[i]      = a + b;
                v[i ^ st] = a - b;
            }
        }
    }

    // ---- Exchange 1 write: float4 slot s = w*128 + j*32 + l, swizzled ----
    #pragma unroll
    for (int j = 0; j < 4; j++) {
        int s  = w * 128 + j * 32 + l;
        int ss = s ^ ((s >> 4) & 7);
        s4[ss] = make_float4(v[4*j+0], v[4*j+1], v[4*j+2], v[4*j+3]);
    }
    __syncthreads();

    // ---- Round 2: thread fixes p=n0n1, q=n6, u=n7n8, w=n9..11; i = n2..5 ----
    const int p  = l & 3;
    const int q  = (l >> 2) & 1;
    const int u  = (l >> 3) & 3;
    const int sbase = 16 * q + 32 * u + 128 * w;   // slot base (i adds 0..15)
    const int sig   = q + 2 * u;                   // = ((s>>4)&7) for these slots
    #pragma unroll
    for (int i = 0; i < RPT; i++) {
        int ss = (sbase + i) ^ sig;
        v[i] = sf[ss * 4 + p];
    }
    // reg index i = n-bits 2..5
    #pragma unroll
    for (int st = 1; st < RPT; st <<= 1) {
        #pragma unroll
        for (int i = 0; i < RPT; i++) {
            if (!(i & st)) {
                float a = v[i], b = v[i ^ st];
                v[i]      = a + b;
                v[i ^ st] = a - b;
            }
        }
    }
    // write back to the same (thread-private) addresses — no barrier needed first
    #pragma unroll
    for (int i = 0; i < RPT; i++) {
        int ss = (sbase + i) ^ sig;
        sf[ss * 4 + p] = v[i];
    }
    __syncthreads();

    // ---- Round 3: thread fixes m = n0..5, u2 = n7n8 ; i2 -> {n6, n9..11} ----
    const int u2 = w >> 1;                 // n7,n8
    const int m  = ((w & 1) << 5) | l;     // n0..5
    const int mq = m >> 2;                 // slot low bits
    const int mp = m & 3;
    #pragma unroll
    for (int i2 = 0; i2 < RPT; i2++) {
        int b6 = i2 & 1, hi = i2 >> 1;
        int s  = mq + 16 * b6 + 32 * u2 + 128 * hi;
        int sg = b6 + 2 * u2;              // = ((s>>4)&7)
        v[i2] = sf[(s ^ sg) * 4 + mp];
    }
    // reg index i2: bit0 = n6, bits1..3 = n9..11
    #pragma unroll
    for (int st = 1; st < RPT; st <<= 1) {
        #pragma unroll
        for (int i = 0; i < RPT; i++) {
            if (!(i & st)) {
                float a = v[i], b = v[i ^ st];
                v[i]      = a + b;
                v[i ^ st] = a - b;
            }
        }
    }

    // ---- Store: n = m + 64*b6 + 128*u2 + 512*hi ; lanes contiguous 128B ----
    const int obase = m + 128 * u2;
    #pragma unroll
    for (int i2 = 0; i2 < RPT; i2++) {
        int b6 = i2 & 1, hi = i2 >> 1;
        y[obase + 64 * b6 + 512 * hi] = v[i2] * 0.015625f;   // * 2^-6
    }
}

extern "C" void kernel_launch(void* const* d_in, const int* in_sizes, int n_in,
                              void* d_out, int out_size)
{
    const float* X = (const float*)d_in[0];   // [8192, 4096] fp32
    // d_in[1]: dense Hadamard matrix H — unused (FWHT).
    float* Y = (float*)d_out;

    const int rows = in_sizes[0] / HN;        // 8192
    fwht_kernel<<<rows, NTHREADS>>>(X, Y);
}